// round 7
// baseline (speedup 1.0000x reference)
#include <cuda_runtime.h>

// out = foldl over T slices: s = (1-lam)*s + lam*adj[t], s0 = adj[0]
// Pure HBM streaming: 272 MB @ T=16, N=2048 — information-floor traffic.
// Pinned at the sm_103a LTS/HBM streaming ceiling (~6.3-6.65 TB/s measured
// across 6 structurally distinct configs). This is the measured argmin config:
// recurrence form (bit-exact), __ldcs/__stcs streaming hints, grid 4096x256,
// regs capped at 32 (occ ~90%).

template <int T>
__global__ void __launch_bounds__(256, 8)
ema_fold_kernel(const float4* __restrict__ adj,
                const float* __restrict__ lam_p,
                float4* __restrict__ out,
                int n4) {
    int i = blockIdx.x * blockDim.x + threadIdx.x;
    if (i >= n4) return;

    const float lam = __ldg(lam_p);
    const float om  = 1.0f - lam;

    const float4* p = adj + i;
    float4 s = __ldcs(p);
#pragma unroll
    for (int t = 1; t < T; ++t) {
        float4 v = __ldcs(p + (size_t)t * (size_t)n4);
        s.x = fmaf(om, s.x, lam * v.x);
        s.y = fmaf(om, s.y, lam * v.y);
        s.z = fmaf(om, s.z, lam * v.z);
        s.w = fmaf(om, s.w, lam * v.w);
    }
    __stcs(out + i, s);
}

// Generic-T fallback (runtime T).
__global__ void __launch_bounds__(256, 8)
ema_fold_generic(const float4* __restrict__ adj,
                 const float* __restrict__ lam_p,
                 float4* __restrict__ out,
                 int n4, int T) {
    int i = blockIdx.x * blockDim.x + threadIdx.x;
    if (i >= n4) return;

    const float lam = __ldg(lam_p);
    const float om  = 1.0f - lam;

    const float4* p = adj + i;
    float4 s = __ldcs(p);
    for (int t = 1; t < T; ++t) {
        float4 v = __ldcs(p + (size_t)t * (size_t)n4);
        s.x = fmaf(om, s.x, lam * v.x);
        s.y = fmaf(om, s.y, lam * v.y);
        s.z = fmaf(om, s.z, lam * v.z);
        s.w = fmaf(om, s.w, lam * v.w);
    }
    __stcs(out + i, s);
}

extern "C" void kernel_launch(void* const* d_in, const int* in_sizes, int n_in,
                              void* d_out, int out_size) {
    const float4* adj  = (const float4*)d_in[0];
    const float*  lamp = (const float*)d_in[1];
    float4*       out  = (float4*)d_out;

    const int total = in_sizes[0];        // T * N * N
    const int T     = total / out_size;   // leading axis length
    const int n4    = out_size / 4;       // float4 elements per slice

    const int threads = 256;
    const int blocks  = (n4 + threads - 1) / threads;

    if (T == 16) {
        ema_fold_kernel<16><<<blocks, threads>>>(adj, lamp, out, n4);
    } else {
        ema_fold_generic<<<blocks, threads>>>(adj, lamp, out, n4, T);
    }
}

// round 8
// speedup vs baseline: 1.0056x; 1.0056x over previous
#include <cuda_runtime.h>

// out = foldl over T slices: s = (1-lam)*s + lam*adj[t], s0 = adj[0]
// Pure HBM streaming: 272 MB @ T=16, N=2048 — information-floor traffic,
// pinned at the sm_103a LTS/HBM streaming ceiling (6.3-6.65 TB/s across
// 7 structurally distinct configs). Final-candidate: recurrence form
// (bit-exact, rel_err=0), plain LDG.128/STG.128, 512-thread blocks.

template <int T, int THREADS>
__global__ void __launch_bounds__(THREADS, 4)
ema_fold_kernel(const float4* __restrict__ adj,
                const float* __restrict__ lam_p,
                float4* __restrict__ out,
                int n4) {
    int i = blockIdx.x * THREADS + threadIdx.x;
    if (i >= n4) return;

    const float lam = __ldg(lam_p);
    const float om  = 1.0f - lam;

    const float4* p = adj + i;
    float4 s = p[0];
#pragma unroll
    for (int t = 1; t < T; ++t) {
        float4 v = p[(size_t)t * (size_t)n4];
        s.x = fmaf(om, s.x, lam * v.x);
        s.y = fmaf(om, s.y, lam * v.y);
        s.z = fmaf(om, s.z, lam * v.z);
        s.w = fmaf(om, s.w, lam * v.w);
    }
    out[i] = s;
}

// Generic-T fallback (runtime T).
__global__ void __launch_bounds__(256, 8)
ema_fold_generic(const float4* __restrict__ adj,
                 const float* __restrict__ lam_p,
                 float4* __restrict__ out,
                 int n4, int T) {
    int i = blockIdx.x * blockDim.x + threadIdx.x;
    if (i >= n4) return;

    const float lam = __ldg(lam_p);
    const float om  = 1.0f - lam;

    const float4* p = adj + i;
    float4 s = p[0];
    for (int t = 1; t < T; ++t) {
        float4 v = p[(size_t)t * (size_t)n4];
        s.x = fmaf(om, s.x, lam * v.x);
        s.y = fmaf(om, s.y, lam * v.y);
        s.z = fmaf(om, s.z, lam * v.z);
        s.w = fmaf(om, s.w, lam * v.w);
    }
    out[i] = s;
}

extern "C" void kernel_launch(void* const* d_in, const int* in_sizes, int n_in,
                              void* d_out, int out_size) {
    const float4* adj  = (const float4*)d_in[0];
    const float*  lamp = (const float*)d_in[1];
    float4*       out  = (float4*)d_out;

    const int total = in_sizes[0];        // T * N * N
    const int T     = total / out_size;   // leading axis length
    const int n4    = out_size / 4;       // float4 elements per slice

    if (T == 16) {
        constexpr int THREADS = 512;
        const int blocks = (n4 + THREADS - 1) / THREADS;
        ema_fold_kernel<16, THREADS><<<blocks, THREADS>>>(adj, lamp, out, n4);
    } else {
        const int threads = 256;
        const int blocks  = (n4 + threads - 1) / threads;
        ema_fold_generic<<<blocks, threads>>>(adj, lamp, out, n4, T);
    }
}